// round 15
// baseline (speedup 1.0000x reference)
#include <cuda_runtime.h>
#include <math.h>

typedef unsigned long long u64;
typedef unsigned int u32;

#define T_   1000
#define B_   16
#define I_   440
#define H_   1024
#define P_   512
#define R_   4096   // 4*H, column-interleaved: col = hh*4 + gate (f,i,o,c)
#define NBLK 128

// smem row stride for frag arrays, in u32 (16B-aligned rows for ldmatrix)
#define FS 12

// ---------------- device scratch (no runtime allocation allowed) ----------------
static __device__ float g_G[(size_t)T_ * B_ * R_];  // 262 MB: input projections [t][b][col]
// A-fragment array for mma: [block][warp][kt][mt][term(hi/lo)][lane*4+r] (u32 bf16x2)
static __device__ u32   g_Af[(size_t)NBLK * 8 * 8 * 2 * 2 * 128];   // 16 MB
static __device__ float g_h[2][H_ * B_];            // double-buffered hidden [buf][k][b]
static __device__ unsigned g_flags[NBLK];           // per-block barrier flags (monotonic)

// ---------------- helpers ----------------
__device__ __forceinline__ u64 pack2(float lo, float hi) {
    u64 r; asm("mov.b64 %0, {%1, %2};" : "=l"(r) : "f"(lo), "f"(hi)); return r;
}
__device__ __forceinline__ void unpack2(u64 v, float& lo, float& hi) {
    asm("mov.b64 {%0, %1}, %2;" : "=f"(lo), "=f"(hi) : "l"(v));
}
__device__ __forceinline__ u64 fadd2(u64 a, u64 b) {
    u64 d; asm("add.rn.f32x2 %0, %1, %2;" : "=l"(d) : "l"(a), "l"(b)); return d;
}

// pack two f32 into bf16x2: low 16 bits = first arg, high 16 bits = second arg
__device__ __forceinline__ u32 bf16x2_of(float lo_elem, float hi_elem) {
    u32 d; asm("cvt.rn.bf16x2.f32 %0, %1, %2;" : "=r"(d) : "f"(hi_elem), "f"(lo_elem));
    return d;
}

__device__ __forceinline__ float tanh_ap(float x) {
    float y; asm("tanh.approx.f32 %0, %1;" : "=f"(y) : "f"(x)); return y;
}
__device__ __forceinline__ float sigmoid_ap(float x) {
    return 0.5f * tanh_ap(0.5f * x) + 0.5f;
}

// mma.sync m16n8k16 bf16 -> f32 accum (row.col)
#define MMA_BF16(d, a, b) \
    asm volatile( \
        "mma.sync.aligned.m16n8k16.row.col.f32.bf16.bf16.f32 " \
        "{%0,%1,%2,%3}, {%4,%5,%6,%7}, {%8,%9}, {%0,%1,%2,%3};\n" \
        : "+f"((d)[0]), "+f"((d)[1]), "+f"((d)[2]), "+f"((d)[3]) \
        : "r"((a)[0]), "r"((a)[1]), "r"((a)[2]), "r"((a)[3]), \
          "r"((b)[0]), "r"((b)[1]))

__device__ __forceinline__ void ldsm_x4(u32& r0, u32& r1, u32& r2, u32& r3, u32 addr) {
    asm volatile("ldmatrix.sync.aligned.m8n8.x4.shared.b16 {%0,%1,%2,%3}, [%4];"
                 : "=r"(r0), "=r"(r1), "=r"(r2), "=r"(r3) : "r"(addr));
}
__device__ __forceinline__ void ldsm_x2(u32& r0, u32& r1, u32 addr) {
    asm volatile("ldmatrix.sync.aligned.m8n8.x2.shared.b16 {%0,%1}, [%2];"
                 : "=r"(r0), "=r"(r1) : "r"(addr));
}

// ---------------- grid barrier v2: per-block flag array ----------------
// Each block release-stores its OWN flag = target; warp 0 acquire-polls all
// 128 flags (4 per lane). No atomic same-address serialization (was 128
// serialized atom.adds at one L2 line), one L2 hop fewer. Flags monotonic
// across graph replays: base is read from the block's own flag at entry
// (only ever written by self -> race-free), no resets, no membar/IVALL.
__device__ __forceinline__ void gsync(unsigned target, int bid) {
    __syncthreads();
    if (threadIdx.x < 32) {
        if (threadIdx.x == 0)
            asm volatile("st.release.gpu.u32 [%0], %1;"
                         :: "l"(&g_flags[bid]), "r"(target) : "memory");
        const unsigned* f = g_flags + threadIdx.x;
        bool done;
        do {
            unsigned v0, v1, v2, v3;
            asm volatile("ld.acquire.gpu.u32 %0, [%1];" : "=r"(v0) : "l"(f)      : "memory");
            asm volatile("ld.acquire.gpu.u32 %0, [%1];" : "=r"(v1) : "l"(f + 32) : "memory");
            asm volatile("ld.acquire.gpu.u32 %0, [%1];" : "=r"(v2) : "l"(f + 64) : "memory");
            asm volatile("ld.acquire.gpu.u32 %0, [%1];" : "=r"(v3) : "l"(f + 96) : "memory");
            bool ok = ((int)(v0 - target) >= 0) && ((int)(v1 - target) >= 0)
                   && ((int)(v2 - target) >= 0) && ((int)(v3 - target) >= 0);
            done = __all_sync(0xffffffffu, ok);
        } while (!done);
    }
    __syncthreads();
}

// ---------------- dummy kernel: shifts ncu's captured launch (-s 5) onto lstm_rec ----
__global__ void dummy_k() {}

// =====================================================================
// Kernel 1 (tensor cores + ldmatrix): G[m][col] = X @ Wcat^T + bias
//   (unchanged from R14: measured as part of the 5233 us total)
// =====================================================================
__global__ __launch_bounds__(256) void gemm_input_tc(
    const float* __restrict__ X,
    const float* __restrict__ wf, const float* __restrict__ wi,
    const float* __restrict__ wo, const float* __restrict__ wc,
    const float* __restrict__ bf, const float* __restrict__ bi,
    const float* __restrict__ bo, const float* __restrict__ bc)
{
    __shared__ __align__(16) u32 Xhi[128 * FS], Xlo[128 * FS];  // [row][kpair0..7]
    __shared__ __align__(16) u32 Whi[64 * FS],  Wlo[64 * FS];

    const int tid  = threadIdx.x;
    const int lane = tid & 31;
    const int wid  = tid >> 5;
    const int wm   = wid >> 1;        // m-group 0..3 (32 rows)
    const int wcg  = wid & 1;         // col-group 0..1 (32 cols)

    const int c0 = blockIdx.x * 64;   // cols (interleaved)
    const int m0 = blockIdx.y * 128;  // rows (t*16+b)

    const int lm  = lane & 3;         // l%4

    const float* wsel[4] = {wf, wi, wo, wc};
    const float* bsel[4] = {bf, bi, bo, bc};

    const int xr0 = tid >> 2;
    const int xr1 = (tid + 256) >> 2;
    const int xj  = tid & 3;
    const int wr  = tid >> 2;
    const int wj  = tid & 3;
    const int wcol = c0 + wr;
    const float* Wrow = wsel[wcol & 3] + (size_t)(wcol >> 2) * I_;

    const u32 xhiB = (u32)__cvta_generic_to_shared(Xhi);
    const u32 xloB = (u32)__cvta_generic_to_shared(Xlo);
    const u32 whiB = (u32)__cvta_generic_to_shared(Whi);
    const u32 wloB = (u32)__cvta_generic_to_shared(Wlo);
    const int arow = wm * 32 + (lane & 7) + 8 * ((lane >> 3) & 1);
    const u32 aoff = (u32)((arow * FS + 4 * (lane >> 4)) * 4);
    const int bl   = lane & 15;
    const u32 boff = (u32)(((wcg * 32 + (bl & 7)) * FS + 4 * (bl >> 3)) * 4);

    float bias0[4], bias1[4];
#pragma unroll
    for (int nt = 0; nt < 4; ++nt) {
        int c = c0 + wcg * 32 + nt * 8 + lm * 2;
        bias0[nt] = bsel[c & 3][c >> 2];
        bias1[nt] = bsel[(c + 1) & 3][(c + 1) >> 2];
    }

    float d[2][4][4];
#pragma unroll
    for (int mt = 0; mt < 2; ++mt)
#pragma unroll
        for (int nt = 0; nt < 4; ++nt)
#pragma unroll
            for (int q = 0; q < 4; ++q) d[mt][nt][q] = 0.f;

    float4 xv0, xv1, wv;
    {
        const int k = 0 + 4 * xj;
        xv0 = (k < I_) ? *(const float4*)(X + (size_t)(m0 + xr0) * I_ + k)
                       : make_float4(0, 0, 0, 0);
        xv1 = (k < I_) ? *(const float4*)(X + (size_t)(m0 + xr1) * I_ + k)
                       : make_float4(0, 0, 0, 0);
        wv  = (k < I_) ? *(const float4*)(Wrow + k) : make_float4(0, 0, 0, 0);
    }

    for (int ks = 0; ks < 28; ++ks) {
        {
            u32 hA = bf16x2_of(xv0.x, xv0.y), hB = bf16x2_of(xv0.z, xv0.w);
            u32 lA = bf16x2_of(xv0.x - __uint_as_float(hA << 16),
                               xv0.y - __uint_as_float(hA & 0xFFFF0000u));
            u32 lB = bf16x2_of(xv0.z - __uint_as_float(hB << 16),
                               xv0.w - __uint_as_float(hB & 0xFFFF0000u));
            Xhi[xr0 * FS + 2 * xj] = hA; Xhi[xr0 * FS + 2 * xj + 1] = hB;
            Xlo[xr0 * FS + 2 * xj] = lA; Xlo[xr0 * FS + 2 * xj + 1] = lB;
            hA = bf16x2_of(xv1.x, xv1.y); hB = bf16x2_of(xv1.z, xv1.w);
            lA = bf16x2_of(xv1.x - __uint_as_float(hA << 16),
                           xv1.y - __uint_as_float(hA & 0xFFFF0000u));
            lB = bf16x2_of(xv1.z - __uint_as_float(hB << 16),
                           xv1.w - __uint_as_float(hB & 0xFFFF0000u));
            Xhi[xr1 * FS + 2 * xj] = hA; Xhi[xr1 * FS + 2 * xj + 1] = hB;
            Xlo[xr1 * FS + 2 * xj] = lA; Xlo[xr1 * FS + 2 * xj + 1] = lB;
            hA = bf16x2_of(wv.x, wv.y); hB = bf16x2_of(wv.z, wv.w);
            lA = bf16x2_of(wv.x - __uint_as_float(hA << 16),
                           wv.y - __uint_as_float(hA & 0xFFFF0000u));
            lB = bf16x2_of(wv.z - __uint_as_float(hB << 16),
                           wv.w - __uint_as_float(hB & 0xFFFF0000u));
            Whi[wr * FS + 2 * wj] = hA; Whi[wr * FS + 2 * wj + 1] = hB;
            Wlo[wr * FS + 2 * wj] = lA; Wlo[wr * FS + 2 * wj + 1] = lB;
        }
        __syncthreads();

        if (ks + 1 < 28) {
            const int k = (ks + 1) * 16 + 4 * xj;
            xv0 = (k < I_) ? *(const float4*)(X + (size_t)(m0 + xr0) * I_ + k)
                           : make_float4(0, 0, 0, 0);
            xv1 = (k < I_) ? *(const float4*)(X + (size_t)(m0 + xr1) * I_ + k)
                           : make_float4(0, 0, 0, 0);
            wv  = (k < I_) ? *(const float4*)(Wrow + k) : make_float4(0, 0, 0, 0);
        }

        u32 ahi[2][4], alo[2][4];
        ldsm_x4(ahi[0][0], ahi[0][1], ahi[0][2], ahi[0][3], xhiB + aoff);
        ldsm_x4(ahi[1][0], ahi[1][1], ahi[1][2], ahi[1][3], xhiB + aoff + 16 * FS * 4);
        ldsm_x4(alo[0][0], alo[0][1], alo[0][2], alo[0][3], xloB + aoff);
        ldsm_x4(alo[1][0], alo[1][1], alo[1][2], alo[1][3], xloB + aoff + 16 * FS * 4);
#pragma unroll
        for (int nt = 0; nt < 4; ++nt) {
            u32 bhi[2], blo[2];
            ldsm_x2(bhi[0], bhi[1], whiB + boff + (u32)(nt * 8 * FS * 4));
            ldsm_x2(blo[0], blo[1], wloB + boff + (u32)(nt * 8 * FS * 4));
#pragma unroll
            for (int mt = 0; mt < 2; ++mt) {
                MMA_BF16(d[mt][nt], ahi[mt], bhi);
                MMA_BF16(d[mt][nt], ahi[mt], blo);
                MMA_BF16(d[mt][nt], alo[mt], bhi);
            }
        }
        __syncthreads();
    }

    const int l4 = lane >> 2;
#pragma unroll
    for (int mt = 0; mt < 2; ++mt) {
        const int row = m0 + wm * 32 + mt * 16 + l4;
#pragma unroll
        for (int nt = 0; nt < 4; ++nt) {
            const int col = c0 + wcg * 32 + nt * 8 + lm * 2;
            *(float2*)(g_G + (size_t)row * R_ + col) =
                make_float2(d[mt][nt][0] + bias0[nt], d[mt][nt][1] + bias1[nt]);
            *(float2*)(g_G + (size_t)(row + 8) * R_ + col) =
                make_float2(d[mt][nt][2] + bias0[nt], d[mt][nt][3] + bias1[nt]);
        }
    }
}

// =====================================================================
// Kernel 2: M[col][k] fragments (unchanged from R8/R14).
// =====================================================================
__global__ __launch_bounds__(256) void gemm_comb(
    const float* __restrict__ wym,
    const float* __restrict__ tf, const float* __restrict__ ti,
    const float* __restrict__ to_, const float* __restrict__ tc)
{
    __shared__ __align__(16) float As[8][128];
    __shared__ __align__(16) float Bs[8][128];

    const int tid = threadIdx.x;
    const int n0  = blockIdx.x * 128;   // cols
    const int m0  = blockIdx.y * 128;   // k

    const int akk = tid >> 5;
    const int amm = (tid & 31) * 4;
    const float* aptr = wym + (size_t)akk * H_ + m0 + amm;

    const int lr = tid >> 1;
    const int lc = (tid & 1) * 4;
    const int bgate = lr & 3;
    const float* Wr = (bgate == 0) ? tf : (bgate == 1) ? ti : (bgate == 2) ? to_ : tc;
    const float* bptr = Wr + (size_t)((n0 >> 2) + (lr >> 2)) * P_ + lc;

    float4 areg = *(const float4*)aptr;
    float4 breg = *(const float4*)bptr;

    const int tm = (tid >> 4) * 8;
    const int tn = (tid & 15) * 8;

    float acc[8][8];
#pragma unroll
    for (int i = 0; i < 8; ++i)
#pragma unroll
        for (int j = 0; j < 8; ++j) acc[i][j] = 0.f;

    for (int k0 = 0; k0 < P_; k0 += 8) {
        *(float4*)&As[akk][amm] = areg;
        Bs[lc + 0][lr] = breg.x; Bs[lc + 1][lr] = breg.y;
        Bs[lc + 2][lr] = breg.z; Bs[lc + 3][lr] = breg.w;
        __syncthreads();
        if (k0 + 8 < P_) {
            areg = *(const float4*)(aptr + (size_t)(k0 + 8) * H_);
            breg = *(const float4*)(bptr + k0 + 8);
        }
#pragma unroll
        for (int kk = 0; kk < 8; ++kk) {
            float a[8], b[8];
            *(float4*)(a)     = *(const float4*)&As[kk][tm];
            *(float4*)(a + 4) = *(const float4*)&As[kk][tm + 4];
            *(float4*)(b)     = *(const float4*)&Bs[kk][tn];
            *(float4*)(b + 4) = *(const float4*)&Bs[kk][tn + 4];
#pragma unroll
            for (int i = 0; i < 8; ++i)
#pragma unroll
                for (int j = 0; j < 8; ++j)
                    acc[i][j] = fmaf(a[i], b[j], acc[i][j]);
        }
        __syncthreads();
    }

#pragma unroll
    for (int i = 0; i < 8; i += 2) {
        const int k = m0 + tm + i;
#pragma unroll
        for (int j = 0; j < 8; ++j) {
            const int col = n0 + tn + j;
            float v0 = acc[i][j], v1 = acc[i + 1][j];
            u32 hi = bf16x2_of(v0, v1);
            float h0 = __uint_as_float(hi << 16);
            float h1 = __uint_as_float(hi & 0xFFFF0000u);
            u32 lo = bf16x2_of(v0 - h0, v1 - h1);
            const int blk  = col >> 5;
            const int warp = k >> 7;
            const int kt   = (k >> 4) & 7;
            const int mt   = (col >> 4) & 1;
            const int r    = ((col >> 3) & 1) | (((k >> 3) & 1) << 1);
            const int lane = ((col & 7) << 2) | ((k & 7) >> 1);
            size_t base = ((((size_t)(blk * 8 + warp) * 8 + kt) * 2 + mt) * 2) * 128;
            g_Af[base + lane * 4 + r]       = hi;
            g_Af[base + 128 + lane * 4 + r] = lo;
        }
    }
}

// =====================================================================
// Kernel 3: persistent recurrence (latency attack):
//   - flag-array barrier (no same-address atomic serialization)
//   - ahi A-fragments persistent in registers (halves per-step A LDGs)
// =====================================================================
#define SM_PART 81920
#define SM_GSM  102400
#define SM_TOT  104704

__global__ __launch_bounds__(256, 1) void lstm_rec(float* __restrict__ out)
{
    extern __shared__ __align__(16) char smem[];
    float* h_s  = (float*)smem;
    float* part = (float*)(smem + SM_PART);
    float* gsm  = (float*)(smem + SM_GSM);

    const int tid  = threadIdx.x;
    const int bid  = blockIdx.x;
    const int wid  = tid >> 5;
    const int lane = tid & 31;

    // per-launch base: own flag (only ever written by this block) -> race-free
    unsigned base;
    asm volatile("ld.relaxed.gpu.u32 %0, [%1];" : "=r"(base) : "l"(&g_flags[bid]) : "memory");

    {
        int i = bid * 256 + tid;
        __stcg(&((float*)g_h)[i], 0.f);
    }

    const int hh0 = bid * 8;
    const int pb  = tid >> 3;
    const int phl = tid & 7;
    float cstate = 0.f;

    const u32* Afbase = g_Af + ((size_t)(bid * 8 + wid) * 8) * 2 * 2 * 128;
    const float* Gbase = g_G + (size_t)pb * R_ + (size_t)(hh0 + phl) * 4;

    const int ln4  = lane >> 2;
    const int lm4  = lane & 3;

    // ---- persistent hi-term A fragments: loaded once, live in registers ----
    u32 ahi_p[8][2][4];
#pragma unroll
    for (int kt = 0; kt < 8; ++kt)
#pragma unroll
        for (int mt = 0; mt < 2; ++mt)
            *(uint4*)ahi_p[kt][mt] =
                *(const uint4*)(Afbase + ((size_t)(kt * 2 + mt) * 2) * 128 + lane * 4);

    gsync(base + 1, bid);

    for (int t = 0; t < T_; ++t) {
        float4 gg;
        if (tid < 128)
            gg = __ldcs((const float4*)(Gbase + (size_t)t * B_ * R_));

        {
            const float4* src = (const float4*)(&g_h[t & 1][0]);
#pragma unroll
            for (int i = 0; i < 16; ++i) {
                int idx = wid * 512 + i * 32 + lane;
                int k  = idx >> 2, bq = idx & 3;
                float4 v = __ldcg(src + idx);
                *(float4*)&h_s[k * 20 + bq * 4] = v;
            }
            __syncwarp();
        }

        float d[2][2][4];
#pragma unroll
        for (int mt = 0; mt < 2; ++mt)
#pragma unroll
            for (int nt = 0; nt < 2; ++nt)
#pragma unroll
                for (int q = 0; q < 4; ++q) d[mt][nt][q] = 0.f;

#pragma unroll
        for (int kt = 0; kt < 8; ++kt) {
            u32 alo[2][4];
#pragma unroll
            for (int mt = 0; mt < 2; ++mt)
                *(uint4*)alo[mt] =
                    *(const uint4*)(Afbase + ((size_t)(kt * 2 + mt) * 2) * 128 + 128 + lane * 4);
            u32 bhi[2][2], blo[2][2];
            const int kb = wid * 128 + kt * 16 + lm4 * 2;
#pragma unroll
            for (int nt = 0; nt < 2; ++nt) {
                const int n = nt * 8 + ln4;
                float f0 = h_s[(kb + 0) * 20 + n];
                float f1 = h_s[(kb + 1) * 20 + n];
                float f2 = h_s[(kb + 8) * 20 + n];
                float f3 = h_s[(kb + 9) * 20 + n];
                u32 p0 = bf16x2_of(f0, f1);
                u32 p1 = bf16x2_of(f2, f3);
                float e0 = f0 - __uint_as_float(p0 << 16);
                float e1 = f1 - __uint_as_float(p0 & 0xFFFF0000u);
                float e2 = f2 - __uint_as_float(p1 << 16);
                float e3 = f3 - __uint_as_float(p1 & 0xFFFF0000u);
                bhi[nt][0] = p0; bhi[nt][1] = p1;
                blo[nt][0] = bf16x2_of(e0, e1);
                blo[nt][1] = bf16x2_of(e2, e3);
            }
#pragma unroll
            for (int mt = 0; mt < 2; ++mt)
#pragma unroll
                for (int nt = 0; nt < 2; ++nt) {
                    MMA_BF16(d[mt][nt], ahi_p[kt][mt], bhi[nt]);
                    MMA_BF16(d[mt][nt], ahi_p[kt][mt], blo[nt]);
                    MMA_BF16(d[mt][nt], alo[mt], bhi[nt]);
                }
        }

#pragma unroll
        for (int mt = 0; mt < 2; ++mt)
#pragma unroll
            for (int nt = 0; nt < 2; ++nt) {
                const int c0 = mt * 16 + ln4;
                const int b  = nt * 8 + lm4 * 2;
                *(float2*)&part[(wid * 32 + c0) * 20 + b] =
                    make_float2(d[mt][nt][0], d[mt][nt][1]);
                *(float2*)&part[(wid * 32 + c0 + 8) * 20 + b] =
                    make_float2(d[mt][nt][2], d[mt][nt][3]);
            }
        __syncthreads();

        {
            const int ri = tid >> 3;
            const int bp = tid & 7;
            u64 s = *(const u64*)&part[(ri) * 20 + 2 * bp];
#pragma unroll
            for (int w = 1; w < 8; ++w)
                s = fadd2(s, *(const u64*)&part[(w * 32 + ri) * 20 + 2 * bp]);
            float lo, hi;
            unpack2(s, lo, hi);
            gsm[(2 * bp) * 36 + ri]     = lo;
            gsm[(2 * bp + 1) * 36 + ri] = hi;
        }
        __syncthreads();

        if (tid < 128) {
            float4 gd = *(const float4*)&gsm[pb * 36 + phl * 4];
            float zf = gg.x + gd.x;
            float zi = gg.y + gd.y;
            float zo = gg.z + gd.z;
            float zc = gg.w + gd.w;
            float ft = sigmoid_ap(zf);
            float it = sigmoid_ap(zi);
            float ot = sigmoid_ap(zo);
            cstate = it * tanh_ap(zc) + ft * cstate;
            float h = ot * tanh_ap(cstate);
            __stcg(&g_h[(t + 1) & 1][(hh0 + phl) * 16 + pb], h);
            __stcs(&out[((size_t)(t * B_ + pb) << 10) + hh0 + phl], h);
            if (t + 1 < T_) {
                const float* np = Gbase + (size_t)(t + 1) * B_ * R_;
                asm volatile("prefetch.global.L2 [%0];" :: "l"(np));
            }
        }

        gsync(base + 2 + t, bid);
    }
}

// =====================================================================
// launch
// =====================================================================
extern "C" void kernel_launch(void* const* d_in, const int* in_sizes, int n_in,
                              void* d_out, int out_size)
{
    const float* x     = (const float*)d_in[0];
    const float* wfx_w = (const float*)d_in[1];
    const float* wfx_b = (const float*)d_in[2];
    const float* wix_w = (const float*)d_in[3];
    const float* wix_b = (const float*)d_in[4];
    const float* wox_w = (const float*)d_in[5];
    const float* wox_b = (const float*)d_in[6];
    const float* wcx_w = (const float*)d_in[7];
    const float* wcx_b = (const float*)d_in[8];
    const float* tfy_w = (const float*)d_in[9];
    const float* tiy_w = (const float*)d_in[10];
    const float* toy_w = (const float*)d_in[11];
    const float* tcy_w = (const float*)d_in[12];
    const float* wym_w = (const float*)d_in[13];
    float* out = (float*)d_out;

    // dummy first: keeps ncu's captured launch (-s 5) on lstm_rec
    dummy_k<<<1, 32>>>();

    // G = x @ Wx^T + b via split-bf16 tensor cores (ldmatrix frag path)
    gemm_input_tc<<<dim3(R_ / 64, 16000 / 128), 256>>>(
        x, wfx_w, wix_w, wox_w, wcx_w, wfx_b, wix_b, wox_b, wcx_b);

    // M fragments for the recurrence
    gemm_comb<<<dim3(R_ / 128, H_ / 128), 256>>>(
        wym_w, tfy_w, tiy_w, toy_w, tcy_w);

    cudaFuncSetAttribute(lstm_rec, cudaFuncAttributeMaxDynamicSharedMemorySize, SM_TOT);
    lstm_rec<<<NBLK, 256, SM_TOT>>>(out);
}